// round 1
// baseline (speedup 1.0000x reference)
#include <cuda_runtime.h>
#include <cstdint>

#define D   128
#define DE  32
#define NET 5
#define MAXN 50000

// ---- scratch (device globals: allocation-free) ----
__device__ float g_S1[(size_t)NET * MAXN * D];    // 128 MB: per-etype sum of src feats
__device__ float g_S2[(size_t)NET * MAXN * DE];   // 32 MB : per-etype sum of edge feats
__device__ float g_cnt[(size_t)NET * MAXN];       // in-degree per etype
__device__ float g_invc[(size_t)NET * MAXN];      // 1/cnt (0 if cnt==0)

// ---------------------------------------------------------------------------
// zero scratch
// ---------------------------------------------------------------------------
__global__ void zero_kernel(int n)
{
    size_t i  = (size_t)blockIdx.x * blockDim.x + threadIdx.x;
    size_t st = (size_t)gridDim.x * blockDim.x;
    float4 z = make_float4(0.f, 0.f, 0.f, 0.f);
    size_t n1 = (size_t)NET * n * D  / 4;
    size_t n2 = (size_t)NET * n * DE / 4;
    size_t n3 = (size_t)NET * n;
    float4* p1 = reinterpret_cast<float4*>(g_S1);
    float4* p2 = reinterpret_cast<float4*>(g_S2);
    for (size_t j = i; j < n1; j += st) p1[j] = z;
    for (size_t j = i; j < n2; j += st) p2[j] = z;
    for (size_t j = i; j < n3; j += st) g_cnt[j] = 0.f;
}

// ---------------------------------------------------------------------------
// scatter: one warp per edge. red.global.add.v4.f32 (sm_90+)
// ---------------------------------------------------------------------------
__device__ __forceinline__ void red_v4(float* p, float4 v)
{
    asm volatile("red.global.add.v4.f32 [%0], {%1, %2, %3, %4};"
                 :: "l"(p), "f"(v.x), "f"(v.y), "f"(v.z), "f"(v.w) : "memory");
}

__global__ void scatter_kernel(const float* __restrict__ x,
                               const float* __restrict__ ef,
                               const int*   __restrict__ src,
                               const int*   __restrict__ dst,
                               int E, int n, int et)
{
    int gw   = (blockIdx.x * blockDim.x + threadIdx.x) >> 5;
    int lane = threadIdx.x & 31;
    if (gw >= E) return;

    int s = __ldg(&src[gw]);
    int d = __ldg(&dst[gw]);

    float* S1 = g_S1 + (size_t)et * n * D;
    float* S2 = g_S2 + (size_t)et * n * DE;
    float* cn = g_cnt + (size_t)et * n;

    // 128 floats of src row: lane handles one float4
    float4 v = __ldg(reinterpret_cast<const float4*>(x + (size_t)s * D) + lane);
    red_v4(S1 + (size_t)d * D + lane * 4, v);

    if (lane < DE / 4) {
        float4 w = __ldg(reinterpret_cast<const float4*>(ef + (size_t)gw * DE) + lane);
        red_v4(S2 + (size_t)d * DE + lane * 4, w);
    }
    if (lane == 0) {
        asm volatile("red.global.add.f32 [%0], %1;" :: "l"(cn + d), "f"(1.0f) : "memory");
    }
}

// ---------------------------------------------------------------------------
// inv-count
// ---------------------------------------------------------------------------
__global__ void invc_kernel(int total)
{
    int i = blockIdx.x * blockDim.x + threadIdx.x;
    if (i < total) {
        float c = g_cnt[i];
        g_invc[i] = (c > 0.f) ? (1.0f / c) : 0.0f;
    }
}

// ---------------------------------------------------------------------------
// fused GEMM + epilogue:
//   acc[n, :] = sum_et (S1_et[n]*invc) @ Wtop_et + (S2_et[n]*invc) @ Wbot_et
//   out = relu(x + (acc + sum_et [cnt_et>0] b_et) / 5)
// 128x128 tile, K = 5*160 in 16-wide chunks, 256 threads, 8x8 microtile
// ---------------------------------------------------------------------------
#define BM 128
#define BN 128
#define BK 16
#define AS_STRIDE 132   // pad to reduce STS bank conflicts, keep 16B alignment

__global__ void __launch_bounds__(256, 2)
gemm_epi_kernel(const float* __restrict__ x,
                const float* __restrict__ W0, const float* __restrict__ W1,
                const float* __restrict__ W2, const float* __restrict__ W3,
                const float* __restrict__ W4,
                const float* __restrict__ b0, const float* __restrict__ b1,
                const float* __restrict__ b2, const float* __restrict__ b3,
                const float* __restrict__ b4,
                float* __restrict__ out, int n)
{
    __shared__ float As[BK][AS_STRIDE];
    __shared__ float Bs[BK][BN];
    __shared__ float invs[NET][BM];
    __shared__ float bsm[NET][D];

    const float* Ws[NET] = {W0, W1, W2, W3, W4};
    const float* bp[NET] = {b0, b1, b2, b3, b4};

    int tid  = threadIdx.x;
    int row0 = blockIdx.x * BM;
    int tx   = tid & 15;   // col group
    int ty   = tid >> 4;   // row group

#pragma unroll
    for (int et = 0; et < NET; et++) {
        if (tid < BM) {
            int row = row0 + tid;
            invs[et][tid] = (row < n) ? g_invc[(size_t)et * n + row] : 0.f;
        }
        if (tid < D) bsm[et][tid] = bp[et][tid];
    }
    __syncthreads();

    float acc[8][8];
#pragma unroll
    for (int i = 0; i < 8; i++)
#pragma unroll
        for (int j = 0; j < 8; j++) acc[i][j] = 0.f;

#pragma unroll
    for (int et = 0; et < NET; et++) {
        const float* __restrict__ W   = Ws[et];
        const float* __restrict__ S1e = g_S1 + (size_t)et * n * D;
        const float* __restrict__ S2e = g_S2 + (size_t)et * n * DE;

        for (int jt = 0; jt < 10; jt++) {   // 10 K-tiles of 16 over the 160 rows of W_et
            // --- A tile: 128 rows x 16 k, scaled by invc on load ---
#pragma unroll
            for (int t = 0; t < 2; t++) {
                int lin = tid + t * 256;
                int r   = lin >> 2;       // 0..127
                int kq  = lin & 3;        // float4 index within BK
                int row = row0 + r;
                float4 v = make_float4(0.f, 0.f, 0.f, 0.f);
                if (row < n) {
                    int j = jt * BK + kq * 4;     // 0..159 within etype
                    const float* sp = (j < D)
                        ? (S1e + (size_t)row * D  + j)
                        : (S2e + (size_t)row * DE + (j - D));
                    v = *reinterpret_cast<const float4*>(sp);
                    float sc = invs[et][r];
                    v.x *= sc; v.y *= sc; v.z *= sc; v.w *= sc;
                }
                As[kq * 4 + 0][r] = v.x;
                As[kq * 4 + 1][r] = v.y;
                As[kq * 4 + 2][r] = v.z;
                As[kq * 4 + 3][r] = v.w;
            }
            // --- B tile: 16 W rows x 128 cols ---
#pragma unroll
            for (int t = 0; t < 2; t++) {
                int lin  = tid + t * 256;
                int colq = lin & 31;   // float4 column
                int kr   = lin >> 5;   // 0..15
                float4 w = *reinterpret_cast<const float4*>(
                    W + (size_t)(jt * BK + kr) * D + colq * 4);
                *reinterpret_cast<float4*>(&Bs[kr][colq * 4]) = w;
            }
            __syncthreads();

#pragma unroll
            for (int kk = 0; kk < BK; kk++) {
                float a[8], b[8];
                *reinterpret_cast<float4*>(&a[0]) =
                    *reinterpret_cast<const float4*>(&As[kk][ty * 8]);
                *reinterpret_cast<float4*>(&a[4]) =
                    *reinterpret_cast<const float4*>(&As[kk][ty * 8 + 4]);
                *reinterpret_cast<float4*>(&b[0]) =
                    *reinterpret_cast<const float4*>(&Bs[kk][tx * 8]);
                *reinterpret_cast<float4*>(&b[4]) =
                    *reinterpret_cast<const float4*>(&Bs[kk][tx * 8 + 4]);
#pragma unroll
                for (int i = 0; i < 8; i++)
#pragma unroll
                    for (int j = 0; j < 8; j++)
                        acc[i][j] += a[i] * b[j];
            }
            __syncthreads();
        }
    }

    // --- epilogue: relu(x + (acc + masked-bias-sum) / 5) ---
#pragma unroll
    for (int i = 0; i < 8; i++) {
        int r   = ty * 8 + i;
        int row = row0 + r;
        if (row >= n) continue;

        float bsum[8];
#pragma unroll
        for (int j = 0; j < 8; j++) bsum[j] = 0.f;
#pragma unroll
        for (int et = 0; et < NET; et++) {
            if (invs[et][r] > 0.f) {
#pragma unroll
                for (int j = 0; j < 8; j++) bsum[j] += bsm[et][tx * 8 + j];
            }
        }
        const float* xr = x + (size_t)row * D + tx * 8;
        float*       orow = out + (size_t)row * D + tx * 8;
        float4 x0 = *reinterpret_cast<const float4*>(xr);
        float4 x1 = *reinterpret_cast<const float4*>(xr + 4);
        float4 o0, o1;
        o0.x = fmaxf(x0.x + (acc[i][0] + bsum[0]) * 0.2f, 0.f);
        o0.y = fmaxf(x0.y + (acc[i][1] + bsum[1]) * 0.2f, 0.f);
        o0.z = fmaxf(x0.z + (acc[i][2] + bsum[2]) * 0.2f, 0.f);
        o0.w = fmaxf(x0.w + (acc[i][3] + bsum[3]) * 0.2f, 0.f);
        o1.x = fmaxf(x1.x + (acc[i][4] + bsum[4]) * 0.2f, 0.f);
        o1.y = fmaxf(x1.y + (acc[i][5] + bsum[5]) * 0.2f, 0.f);
        o1.z = fmaxf(x1.z + (acc[i][6] + bsum[6]) * 0.2f, 0.f);
        o1.w = fmaxf(x1.w + (acc[i][7] + bsum[7]) * 0.2f, 0.f);
        *reinterpret_cast<float4*>(orow)     = o0;
        *reinterpret_cast<float4*>(orow + 4) = o1;
    }
}

// ---------------------------------------------------------------------------
extern "C" void kernel_launch(void* const* d_in, const int* in_sizes, int n_in,
                              void* d_out, int out_size)
{
    const float* x = (const float*)d_in[0];
    int n = in_sizes[0] / D;
    if (n > MAXN) return;  // scratch sized for the problem's N

    const float *ef[NET], *W[NET], *b[NET];
    const int   *src[NET], *dst[NET];
    int E[NET];
    for (int et = 0; et < NET; et++) {
        ef[et]  = (const float*)d_in[1 + 5 * et + 0];
        W[et]   = (const float*)d_in[1 + 5 * et + 1];
        b[et]   = (const float*)d_in[1 + 5 * et + 2];
        src[et] = (const int*)  d_in[1 + 5 * et + 3];
        dst[et] = (const int*)  d_in[1 + 5 * et + 4];
        E[et]   = in_sizes[1 + 5 * et + 3];
    }
    float* out = (float*)d_out;

    // 1) zero scratch
    zero_kernel<<<2048, 256>>>(n);

    // 2) per-etype scatter (sequential launches keep per-etype working set in L2)
    for (int et = 0; et < NET; et++) {
        if (E[et] <= 0) continue;
        int warps  = E[et];
        int blocks = (warps * 32 + 255) / 256;
        scatter_kernel<<<blocks, 256>>>(x, ef[et], src[et], dst[et], E[et], n, et);
    }

    // 3) inverse counts
    {
        int total  = NET * n;
        int blocks = (total + 255) / 256;
        invc_kernel<<<blocks, 256>>>(total);
    }

    // 4) fused GEMM + epilogue
    {
        int blocks = (n + BM - 1) / BM;
        gemm_epi_kernel<<<blocks, 256>>>(x,
                                         W[0], W[1], W[2], W[3], W[4],
                                         b[0], b[1], b[2], b[3], b[4],
                                         out, n);
    }
}

// round 2
// speedup vs baseline: 1.4112x; 1.4112x over previous
#include <cuda_runtime.h>
#include <cstdint>

#define D    128
#define DE   32
#define NET  5
#define MAXN 50000
#define CAP_TOTAL 4000000   // total CSR slots across all etypes

// ---- scratch (device globals: allocation-free) ----
__device__ float g_S1[(size_t)NET * MAXN * D];    // pre-scaled per-etype mean of src feats
__device__ float g_S2[(size_t)NET * MAXN * DE];   // pre-scaled per-etype mean of edge feats
__device__ float g_mask[(size_t)NET * MAXN];      // 1 if deg>0 else 0
__device__ int   g_deg[(size_t)NET * MAXN];       // in-degree per (etype,node)
__device__ int   g_off[(size_t)NET * MAXN];       // exclusive CSR offsets (concatenated)
__device__ int   g_cur[(size_t)NET * MAXN];       // fill cursors
__device__ int2  g_csr[(size_t)CAP_TOTAL];        // (src, edge_id) per slot
__device__ int   g_bsum[512];
__device__ int   g_bscan[512];

struct EdgeMeta {
    const int*   src[NET];
    const int*   dst[NET];
    const float* ef[NET];
    int          E[NET];
};

// ---------------------------------------------------------------------------
// 0) zero degrees
// ---------------------------------------------------------------------------
__global__ void zero_deg_kernel(int nelem)
{
    int i = blockIdx.x * blockDim.x + threadIdx.x;
    if (i < nelem) g_deg[i] = 0;
}

// ---------------------------------------------------------------------------
// 1) count degrees (all etypes, grid.y = etype)
// ---------------------------------------------------------------------------
__global__ void count_kernel(EdgeMeta em, int n)
{
    int et = blockIdx.y;
    int i  = blockIdx.x * blockDim.x + threadIdx.x;
    if (i < em.E[et]) {
        int d = __ldg(&em.dst[et][i]);
        atomicAdd(&g_deg[et * n + d], 1);
    }
}

// ---------------------------------------------------------------------------
// 2) prefix scan (3 kernels, chunk = 2048)
// ---------------------------------------------------------------------------
__global__ void scan_part_kernel(int nelem)
{
    __shared__ int sm[256];
    int tid  = threadIdx.x;
    int base = blockIdx.x * 2048;
    int s = 0;
    for (int j = tid; j < 2048; j += 256) {
        int i = base + j;
        s += (i < nelem) ? g_deg[i] : 0;
    }
    sm[tid] = s; __syncthreads();
    for (int o = 128; o > 0; o >>= 1) {
        if (tid < o) sm[tid] += sm[tid + o];
        __syncthreads();
    }
    if (tid == 0) g_bsum[blockIdx.x] = sm[0];
}

__global__ void scan_top_kernel(int nblk)
{
    __shared__ int sm[256];
    int tid = threadIdx.x;
    sm[tid] = (tid < nblk) ? g_bsum[tid] : 0;
    __syncthreads();
    for (int o = 1; o < 256; o <<= 1) {
        int t = (tid >= o) ? sm[tid - o] : 0;
        __syncthreads();
        sm[tid] += t;
        __syncthreads();
    }
    if (tid < nblk) g_bscan[tid] = (tid > 0) ? sm[tid - 1] : 0;
}

__global__ void scan_final_kernel(int nelem)
{
    __shared__ int tsum[256];
    int tid  = threadIdx.x;
    int base = blockIdx.x * 2048 + tid * 8;
    int v[8], pre[8];
    int s = 0;
#pragma unroll
    for (int j = 0; j < 8; j++) {
        int i = base + j;
        v[j] = (i < nelem) ? g_deg[i] : 0;
        pre[j] = s;
        s += v[j];
    }
    tsum[tid] = s; __syncthreads();
    for (int o = 1; o < 256; o <<= 1) {
        int t = (tid >= o) ? tsum[tid - o] : 0;
        __syncthreads();
        tsum[tid] += t;
        __syncthreads();
    }
    int off = g_bscan[blockIdx.x] + ((tid > 0) ? tsum[tid - 1] : 0);
#pragma unroll
    for (int j = 0; j < 8; j++) {
        int i = base + j;
        if (i < nelem) {
            g_off[i] = off + pre[j];
            g_cur[i] = off + pre[j];
        }
    }
}

// ---------------------------------------------------------------------------
// 3) fill CSR slots: (src, edge_id) packed as int2
// ---------------------------------------------------------------------------
__global__ void fill_kernel(EdgeMeta em, int n)
{
    int et = blockIdx.y;
    int i  = blockIdx.x * blockDim.x + threadIdx.x;
    if (i < em.E[et]) {
        int d = __ldg(&em.dst[et][i]);
        int s = __ldg(&em.src[et][i]);
        int pos = atomicAdd(&g_cur[et * n + d], 1);
        g_csr[pos] = make_int2(s, i);
    }
}

// ---------------------------------------------------------------------------
// 4) gather-aggregate: one warp per (etype,node). Writes mean(src feats) and
//    mean(edge feats) pre-scaled by 1/deg.
// ---------------------------------------------------------------------------
__global__ void __launch_bounds__(256)
gather_kernel(const float* __restrict__ x, EdgeMeta em, int n)
{
    int gw   = (blockIdx.x * blockDim.x + threadIdx.x) >> 5;
    int lane = threadIdx.x & 31;
    int total = NET * n;
    if (gw >= total) return;

    int et   = gw / n;
    const float* __restrict__ ef =
        (et == 0) ? em.ef[0] : (et == 1) ? em.ef[1] : (et == 2) ? em.ef[2]
                  : (et == 3) ? em.ef[3] : em.ef[4];

    int beg = g_off[gw];
    int cnt = g_deg[gw];

    float4 a1 = make_float4(0.f, 0.f, 0.f, 0.f);
    float  a2 = 0.f;

    for (int e = beg; e < beg + cnt; e++) {
        int2 m = __ldg(&g_csr[e]);                       // broadcast LDG.64
        float4 v = __ldg(reinterpret_cast<const float4*>(x + (size_t)m.x * D) + lane);
        a1.x += v.x; a1.y += v.y; a1.z += v.z; a1.w += v.w;
        a2 += __ldg(&ef[(size_t)m.y * DE + lane]);
    }

    float inv = (cnt > 0) ? (1.0f / (float)cnt) : 0.0f;
    a1.x *= inv; a1.y *= inv; a1.z *= inv; a1.w *= inv;
    a2 *= inv;

    *(reinterpret_cast<float4*>(g_S1 + (size_t)gw * D) + lane) = a1;
    g_S2[(size_t)gw * DE + lane] = a2;
    if (lane == 0) g_mask[gw] = (cnt > 0) ? 1.0f : 0.0f;
}

// ---------------------------------------------------------------------------
// packed fp32 helpers (FFMA2 — PTX-only on sm_103a)
// ---------------------------------------------------------------------------
__device__ __forceinline__ unsigned long long pk2(float lo, float hi)
{
    unsigned long long r;
    asm("mov.b64 %0, {%1, %2};" : "=l"(r) : "f"(lo), "f"(hi));
    return r;
}
__device__ __forceinline__ void unpk2(float& lo, float& hi, unsigned long long v)
{
    asm("mov.b64 {%0, %1}, %2;" : "=f"(lo), "=f"(hi) : "l"(v));
}
__device__ __forceinline__ void ffma2(unsigned long long& d,
                                      unsigned long long a, unsigned long long b)
{
    asm("fma.rn.f32x2 %0, %1, %2, %3;" : "=l"(d) : "l"(a), "l"(b), "l"(d));
}

// ---------------------------------------------------------------------------
// 5) fused GEMM + epilogue (FFMA2 microkernel):
//    acc[n,:] = sum_et  M1_et[n] @ Wtop_et + M2_et[n] @ Wbot_et  (pre-scaled)
//    out = relu(x + (acc + sum_et mask_et * b_et) * 0.2)
// ---------------------------------------------------------------------------
#define BM 128
#define BN 128
#define BK 16
#define AS_STRIDE 132

__global__ void __launch_bounds__(256, 2)
gemm_epi_kernel(const float* __restrict__ x,
                const float* __restrict__ W0, const float* __restrict__ W1,
                const float* __restrict__ W2, const float* __restrict__ W3,
                const float* __restrict__ W4,
                const float* __restrict__ b0, const float* __restrict__ b1,
                const float* __restrict__ b2, const float* __restrict__ b3,
                const float* __restrict__ b4,
                float* __restrict__ out, int n)
{
    __shared__ float As[BK][AS_STRIDE];
    __shared__ float Bs[BK][BN];
    __shared__ float msk[NET][BM];
    __shared__ float bsm[NET][D];

    const float* Ws[NET] = {W0, W1, W2, W3, W4};
    const float* bp[NET] = {b0, b1, b2, b3, b4};

    int tid  = threadIdx.x;
    int row0 = blockIdx.x * BM;
    int tx   = tid & 15;
    int ty   = tid >> 4;

#pragma unroll
    for (int et = 0; et < NET; et++) {
        if (tid < BM) {
            int row = row0 + tid;
            msk[et][tid] = (row < n) ? g_mask[(size_t)et * n + row] : 0.f;
        }
        if (tid < D) bsm[et][tid] = bp[et][tid];
    }
    __syncthreads();

    unsigned long long accp[8][4];
#pragma unroll
    for (int i = 0; i < 8; i++)
#pragma unroll
        for (int j = 0; j < 4; j++) accp[i][j] = 0ULL;

#pragma unroll
    for (int et = 0; et < NET; et++) {
        const float* __restrict__ W   = Ws[et];
        const float* __restrict__ S1e = g_S1 + (size_t)et * n * D;
        const float* __restrict__ S2e = g_S2 + (size_t)et * n * DE;

        for (int jt = 0; jt < 10; jt++) {
            // --- A tile (pre-scaled means): 128 rows x 16 k ---
#pragma unroll
            for (int t = 0; t < 2; t++) {
                int lin = tid + t * 256;
                int r   = lin >> 2;
                int kq  = lin & 3;
                int row = row0 + r;
                float4 v = make_float4(0.f, 0.f, 0.f, 0.f);
                if (row < n) {
                    int j = jt * BK + kq * 4;
                    const float* sp = (j < D)
                        ? (S1e + (size_t)row * D  + j)
                        : (S2e + (size_t)row * DE + (j - D));
                    v = *reinterpret_cast<const float4*>(sp);
                }
                As[kq * 4 + 0][r] = v.x;
                As[kq * 4 + 1][r] = v.y;
                As[kq * 4 + 2][r] = v.z;
                As[kq * 4 + 3][r] = v.w;
            }
            // --- B tile: 16 W rows x 128 cols ---
#pragma unroll
            for (int t = 0; t < 2; t++) {
                int lin  = tid + t * 256;
                int colq = lin & 31;
                int kr   = lin >> 5;
                float4 w = *reinterpret_cast<const float4*>(
                    W + (size_t)(jt * BK + kr) * D + colq * 4);
                *reinterpret_cast<float4*>(&Bs[kr][colq * 4]) = w;
            }
            __syncthreads();

#pragma unroll
            for (int kk = 0; kk < BK; kk++) {
                float a[8], b[8];
                *reinterpret_cast<float4*>(&a[0]) =
                    *reinterpret_cast<const float4*>(&As[kk][ty * 8]);
                *reinterpret_cast<float4*>(&a[4]) =
                    *reinterpret_cast<const float4*>(&As[kk][ty * 8 + 4]);
                *reinterpret_cast<float4*>(&b[0]) =
                    *reinterpret_cast<const float4*>(&Bs[kk][tx * 8]);
                *reinterpret_cast<float4*>(&b[4]) =
                    *reinterpret_cast<const float4*>(&Bs[kk][tx * 8 + 4]);

                unsigned long long bb[4];
#pragma unroll
                for (int j = 0; j < 4; j++) bb[j] = pk2(b[2 * j], b[2 * j + 1]);
#pragma unroll
                for (int i = 0; i < 8; i++) {
                    unsigned long long aa = pk2(a[i], a[i]);
#pragma unroll
                    for (int j = 0; j < 4; j++) ffma2(accp[i][j], aa, bb[j]);
                }
            }
            __syncthreads();
        }
    }

    // --- epilogue: relu(x + (acc + masked-bias-sum) * 0.2) ---
#pragma unroll
    for (int i = 0; i < 8; i++) {
        int r   = ty * 8 + i;
        int row = row0 + r;
        if (row >= n) continue;

        float accf[8];
#pragma unroll
        for (int j = 0; j < 4; j++) unpk2(accf[2 * j], accf[2 * j + 1], accp[i][j]);

        float bsum[8];
#pragma unroll
        for (int j = 0; j < 8; j++) bsum[j] = 0.f;
#pragma unroll
        for (int et = 0; et < NET; et++) {
            if (msk[et][r] > 0.f) {
#pragma unroll
                for (int j = 0; j < 8; j++) bsum[j] += bsm[et][tx * 8 + j];
            }
        }
        const float* xr   = x   + (size_t)row * D + tx * 8;
        float*       orow = out + (size_t)row * D + tx * 8;
        float4 x0 = *reinterpret_cast<const float4*>(xr);
        float4 x1 = *reinterpret_cast<const float4*>(xr + 4);
        float4 o0, o1;
        o0.x = fmaxf(x0.x + (accf[0] + bsum[0]) * 0.2f, 0.f);
        o0.y = fmaxf(x0.y + (accf[1] + bsum[1]) * 0.2f, 0.f);
        o0.z = fmaxf(x0.z + (accf[2] + bsum[2]) * 0.2f, 0.f);
        o0.w = fmaxf(x0.w + (accf[3] + bsum[3]) * 0.2f, 0.f);
        o1.x = fmaxf(x1.x + (accf[4] + bsum[4]) * 0.2f, 0.f);
        o1.y = fmaxf(x1.y + (accf[5] + bsum[5]) * 0.2f, 0.f);
        o1.z = fmaxf(x1.z + (accf[6] + bsum[6]) * 0.2f, 0.f);
        o1.w = fmaxf(x1.w + (accf[7] + bsum[7]) * 0.2f, 0.f);
        *reinterpret_cast<float4*>(orow)     = o0;
        *reinterpret_cast<float4*>(orow + 4) = o1;
    }
}

// ---------------------------------------------------------------------------
extern "C" void kernel_launch(void* const* d_in, const int* in_sizes, int n_in,
                              void* d_out, int out_size)
{
    const float* x = (const float*)d_in[0];
    int n = in_sizes[0] / D;
    if (n > MAXN) return;

    EdgeMeta em;
    const float *W[NET], *b[NET];
    int maxE = 0, totE = 0;
    for (int et = 0; et < NET; et++) {
        em.ef[et]  = (const float*)d_in[1 + 5 * et + 0];
        W[et]      = (const float*)d_in[1 + 5 * et + 1];
        b[et]      = (const float*)d_in[1 + 5 * et + 2];
        em.src[et] = (const int*)  d_in[1 + 5 * et + 3];
        em.dst[et] = (const int*)  d_in[1 + 5 * et + 4];
        em.E[et]   = in_sizes[1 + 5 * et + 3];
        if (em.E[et] > maxE) maxE = em.E[et];
        totE += em.E[et];
    }
    if (totE > CAP_TOTAL) return;
    float* out = (float*)d_out;

    int nelem = NET * n;
    int nblk  = (nelem + 2047) / 2048;   // <= 256 for MAXN

    // 0) zero degrees
    zero_deg_kernel<<<(nelem + 255) / 256, 256>>>(nelem);

    // 1) count
    {
        dim3 grid((maxE + 255) / 256, NET);
        count_kernel<<<grid, 256>>>(em, n);
    }

    // 2) scan
    scan_part_kernel<<<nblk, 256>>>(nelem);
    scan_top_kernel<<<1, 256>>>(nblk);
    scan_final_kernel<<<nblk, 256>>>(nelem);

    // 3) fill CSR
    {
        dim3 grid((maxE + 255) / 256, NET);
        fill_kernel<<<grid, 256>>>(em, n);
    }

    // 4) gather-aggregate
    {
        int warps  = nelem;
        int blocks = (warps * 32 + 255) / 256;
        gather_kernel<<<blocks, 256>>>(x, em, n);
    }

    // 5) fused GEMM + epilogue
    {
        int blocks = (n + BM - 1) / BM;
        gemm_epi_kernel<<<blocks, 256>>>(x,
                                         W[0], W[1], W[2], W[3], W[4],
                                         b[0], b[1], b[2], b[3], b[4],
                                         out, n);
    }
}

// round 3
// speedup vs baseline: 1.6291x; 1.1545x over previous
#include <cuda_runtime.h>
#include <cuda_fp16.h>
#include <cstdint>

#define D    128
#define DE   32
#define NET  5
#define MAXN 50000
#define CAP_TOTAL 4000000   // total CSR slots across all etypes
#define KW   (D + DE)       // 160

// ---- scratch (device globals: allocation-free) ----
__device__ float  g_S1[(size_t)NET * MAXN * D];    // tf32-rounded per-etype mean of src feats
__device__ float  g_S2[(size_t)NET * MAXN * DE];   // tf32-rounded per-etype mean of edge feats
__device__ float  g_mask[(size_t)NET * MAXN];      // 1 if deg>0 else 0
__device__ int    g_deg[(size_t)NET * MAXN];
__device__ int    g_off[(size_t)NET * MAXN];
__device__ int    g_cur[(size_t)NET * MAXN];
__device__ int2   g_csr[(size_t)CAP_TOTAL];        // (src, edge_id)
__device__ int    g_bsum[512];
__device__ int    g_bscan[512];
__device__ __half g_xh[(size_t)MAXN * D];          // fp16 copy of op_feats
__device__ float  g_Wt[(size_t)NET * KW * D];      // tf32-rounded weights

struct EdgeMeta {
    const int*   src[NET];
    const int*   dst[NET];
    const float* ef[NET];
    int          E[NET];
};
struct WPtrs { const float* W[NET]; };

__device__ __forceinline__ float tf32r(float v)
{
    unsigned u;
    asm("cvt.rna.tf32.f32 %0, %1;" : "=r"(u) : "f"(v));
    return __uint_as_float(u);
}

// ---------------------------------------------------------------------------
// convert x -> fp16
// ---------------------------------------------------------------------------
__global__ void conv_x_kernel(const float* __restrict__ x, int total4)
{
    int i = blockIdx.x * blockDim.x + threadIdx.x;
    if (i < total4) {
        float4 v = reinterpret_cast<const float4*>(x)[i];
        __half2 h0 = __floats2half2_rn(v.x, v.y);
        __half2 h1 = __floats2half2_rn(v.z, v.w);
        uint2 u;
        u.x = *reinterpret_cast<unsigned*>(&h0);
        u.y = *reinterpret_cast<unsigned*>(&h1);
        reinterpret_cast<uint2*>(g_xh)[i] = u;
    }
}

// ---------------------------------------------------------------------------
// convert W -> tf32-rounded fp32
// ---------------------------------------------------------------------------
__global__ void conv_w_kernel(WPtrs wp, int per)
{
    int et = blockIdx.y;
    int i  = blockIdx.x * blockDim.x + threadIdx.x;
    const float* W = (et == 0) ? wp.W[0] : (et == 1) ? wp.W[1] : (et == 2) ? wp.W[2]
                   : (et == 3) ? wp.W[3] : wp.W[4];
    if (i < per) g_Wt[(size_t)et * per + i] = tf32r(__ldg(&W[i]));
}

// ---------------------------------------------------------------------------
// CSR build: zero / count / scan / fill
// ---------------------------------------------------------------------------
__global__ void zero_deg_kernel(int nelem)
{
    int i = blockIdx.x * blockDim.x + threadIdx.x;
    if (i < nelem) g_deg[i] = 0;
}

__global__ void count_kernel(EdgeMeta em, int n)
{
    int et = blockIdx.y;
    int i  = blockIdx.x * blockDim.x + threadIdx.x;
    const int* dst = (et == 0) ? em.dst[0] : (et == 1) ? em.dst[1] : (et == 2) ? em.dst[2]
                   : (et == 3) ? em.dst[3] : em.dst[4];
    int E = em.E[et];
    if (i < E) atomicAdd(&g_deg[et * n + __ldg(&dst[i])], 1);
}

__global__ void scan_part_kernel(int nelem)
{
    __shared__ int sm[256];
    int tid  = threadIdx.x;
    int base = blockIdx.x * 2048;
    int s = 0;
    for (int j = tid; j < 2048; j += 256) {
        int i = base + j;
        s += (i < nelem) ? g_deg[i] : 0;
    }
    sm[tid] = s; __syncthreads();
    for (int o = 128; o > 0; o >>= 1) {
        if (tid < o) sm[tid] += sm[tid + o];
        __syncthreads();
    }
    if (tid == 0) g_bsum[blockIdx.x] = sm[0];
}

__global__ void scan_top_kernel(int nblk)
{
    __shared__ int sm[256];
    int tid = threadIdx.x;
    sm[tid] = (tid < nblk) ? g_bsum[tid] : 0;
    __syncthreads();
    for (int o = 1; o < 256; o <<= 1) {
        int t = (tid >= o) ? sm[tid - o] : 0;
        __syncthreads();
        sm[tid] += t;
        __syncthreads();
    }
    if (tid < nblk) g_bscan[tid] = (tid > 0) ? sm[tid - 1] : 0;
}

__global__ void scan_final_kernel(int nelem)
{
    __shared__ int tsum[256];
    int tid  = threadIdx.x;
    int base = blockIdx.x * 2048 + tid * 8;
    int v[8], pre[8];
    int s = 0;
#pragma unroll
    for (int j = 0; j < 8; j++) {
        int i = base + j;
        v[j] = (i < nelem) ? g_deg[i] : 0;
        pre[j] = s;
        s += v[j];
    }
    tsum[tid] = s; __syncthreads();
    for (int o = 1; o < 256; o <<= 1) {
        int t = (tid >= o) ? tsum[tid - o] : 0;
        __syncthreads();
        tsum[tid] += t;
        __syncthreads();
    }
    int off = g_bscan[blockIdx.x] + ((tid > 0) ? tsum[tid - 1] : 0);
#pragma unroll
    for (int j = 0; j < 8; j++) {
        int i = base + j;
        if (i < nelem) {
            g_off[i] = off + pre[j];
            g_cur[i] = off + pre[j];
        }
    }
}

__global__ void fill_kernel(EdgeMeta em, int n)
{
    int et = blockIdx.y;
    int i  = blockIdx.x * blockDim.x + threadIdx.x;
    const int* dst = (et == 0) ? em.dst[0] : (et == 1) ? em.dst[1] : (et == 2) ? em.dst[2]
                   : (et == 3) ? em.dst[3] : em.dst[4];
    const int* src = (et == 0) ? em.src[0] : (et == 1) ? em.src[1] : (et == 2) ? em.src[2]
                   : (et == 3) ? em.src[3] : em.src[4];
    int E = em.E[et];
    if (i < E) {
        int d = __ldg(&dst[i]);
        int s = __ldg(&src[i]);
        int pos = atomicAdd(&g_cur[et * n + d], 1);
        g_csr[pos] = make_int2(s, i);
    }
}

// ---------------------------------------------------------------------------
// gather-aggregate: one warp per (etype,node), shfl-batched CSR, fp16 x.
// Output: tf32-rounded means.
// ---------------------------------------------------------------------------
__global__ void __launch_bounds__(256)
gather_kernel(EdgeMeta em, int n)
{
    int gw   = (blockIdx.x * blockDim.x + threadIdx.x) >> 5;
    int lane = threadIdx.x & 31;
    if (gw >= NET * n) return;

    int et = gw / n;
    const float* __restrict__ ef =
        (et == 0) ? em.ef[0] : (et == 1) ? em.ef[1] : (et == 2) ? em.ef[2]
                  : (et == 3) ? em.ef[3] : em.ef[4];

    int beg = g_off[gw];
    int cnt = g_deg[gw];
    int end = beg + cnt;

    float4 a1 = make_float4(0.f, 0.f, 0.f, 0.f);
    float  a2 = 0.f;

    for (int base = beg; base < end; base += 32) {
        int take = min(32, end - base);
        int2 mm = make_int2(0, 0);
        if (lane < take) mm = __ldg(&g_csr[base + lane]);
#pragma unroll 4
        for (int j = 0; j < take; j++) {
            int sidx = __shfl_sync(0xffffffffu, mm.x, j);
            int eidx = __shfl_sync(0xffffffffu, mm.y, j);
            uint2 hv = __ldg(reinterpret_cast<const uint2*>(g_xh + (size_t)sidx * D) + lane);
            __half2 h0 = *reinterpret_cast<__half2*>(&hv.x);
            __half2 h1 = *reinterpret_cast<__half2*>(&hv.y);
            float2 f0 = __half22float2(h0);
            float2 f1 = __half22float2(h1);
            a1.x += f0.x; a1.y += f0.y; a1.z += f1.x; a1.w += f1.y;
            a2 += __ldg(&ef[(size_t)eidx * DE + lane]);
        }
    }

    float inv = (cnt > 0) ? (1.0f / (float)cnt) : 0.0f;
    a1.x = tf32r(a1.x * inv);
    a1.y = tf32r(a1.y * inv);
    a1.z = tf32r(a1.z * inv);
    a1.w = tf32r(a1.w * inv);
    a2   = tf32r(a2 * inv);

    *(reinterpret_cast<float4*>(g_S1 + (size_t)gw * D) + lane) = a1;
    g_S2[(size_t)gw * DE + lane] = a2;
    if (lane == 0) g_mask[gw] = (cnt > 0) ? 1.0f : 0.0f;
}

// ---------------------------------------------------------------------------
// fused GEMM (tf32 HMMA) + epilogue:
//   acc[n,:] = sum_et M1_et[n] @ Wtop_et + M2_et[n] @ Wbot_et
//   out = relu(x + (acc + sum_et mask_et * b_et) * 0.2)
// CTA 128x128, 8 warps in 2(M)x4(N), warp tile 64x32, mma m16n8k8 tf32.
// ---------------------------------------------------------------------------
#define BM 128
#define BN 128
#define BKT 16
#define SA 132

__device__ __forceinline__ void mma_tf32(float* c, const float* a, const float* b)
{
    asm volatile(
        "mma.sync.aligned.m16n8k8.row.col.f32.tf32.tf32.f32 "
        "{%0,%1,%2,%3}, {%4,%5,%6,%7}, {%8,%9}, {%0,%1,%2,%3};"
        : "+f"(c[0]), "+f"(c[1]), "+f"(c[2]), "+f"(c[3])
        : "r"(__float_as_uint(a[0])), "r"(__float_as_uint(a[1])),
          "r"(__float_as_uint(a[2])), "r"(__float_as_uint(a[3])),
          "r"(__float_as_uint(b[0])), "r"(__float_as_uint(b[1])));
}

__global__ void __launch_bounds__(256, 2)
gemm_epi_kernel(const float* __restrict__ x,
                const float* __restrict__ b0, const float* __restrict__ b1,
                const float* __restrict__ b2, const float* __restrict__ b3,
                const float* __restrict__ b4,
                float* __restrict__ out, int n)
{
    __shared__ float As[BKT][SA];
    __shared__ float Bs[BKT][SA];
    __shared__ float msk[NET][BM];
    __shared__ float bsm[NET][D];

    const float* bp[NET] = {b0, b1, b2, b3, b4};

    int tid  = threadIdx.x;
    int lane = tid & 31;
    int warp = tid >> 5;
    int wm   = (warp & 1) * 64;   // warp M origin
    int wn   = (warp >> 1) * 32;  // warp N origin
    int lrow = lane >> 2;
    int lcol = lane & 3;
    int row0 = blockIdx.x * BM;

#pragma unroll
    for (int et = 0; et < NET; et++) {
        if (tid < BM) {
            int row = row0 + tid;
            msk[et][tid] = (row < n) ? g_mask[(size_t)et * n + row] : 0.f;
        }
        if (tid < D) bsm[et][tid] = bp[et][tid];
    }

    float c[4][4][4];
#pragma unroll
    for (int s = 0; s < 4; s++)
#pragma unroll
        for (int t = 0; t < 4; t++)
#pragma unroll
            for (int r = 0; r < 4; r++) c[s][t][r] = 0.f;

#pragma unroll
    for (int et = 0; et < NET; et++) {
        const float* __restrict__ S1e = g_S1 + (size_t)et * n * D;
        const float* __restrict__ S2e = g_S2 + (size_t)et * n * DE;
        const float* __restrict__ Wt  = g_Wt + (size_t)et * KW * D;

        for (int jt = 0; jt < 10; jt++) {
            // --- A tile: 128 rows x 16 k ---
#pragma unroll
            for (int t = 0; t < 2; t++) {
                int lin = tid + t * 256;
                int r   = lin >> 2;
                int kq  = lin & 3;
                int row = row0 + r;
                float4 v = make_float4(0.f, 0.f, 0.f, 0.f);
                if (row < n) {
                    int j = jt * BKT + kq * 4;
                    const float* sp = (j < D)
                        ? (S1e + (size_t)row * D  + j)
                        : (S2e + (size_t)row * DE + (j - D));
                    v = *reinterpret_cast<const float4*>(sp);
                }
                As[kq * 4 + 0][r] = v.x;
                As[kq * 4 + 1][r] = v.y;
                As[kq * 4 + 2][r] = v.z;
                As[kq * 4 + 3][r] = v.w;
            }
            // --- B tile: 16 k x 128 n ---
#pragma unroll
            for (int t = 0; t < 2; t++) {
                int lin  = tid + t * 256;
                int colq = lin & 31;
                int kr   = lin >> 5;
                float4 w = *reinterpret_cast<const float4*>(
                    Wt + (size_t)(jt * BKT + kr) * D + colq * 4);
                *reinterpret_cast<float4*>(&Bs[kr][colq * 4]) = w;
            }
            __syncthreads();

#pragma unroll
            for (int k8 = 0; k8 < BKT; k8 += 8) {
                float a[4][4], b[4][2];
#pragma unroll
                for (int s = 0; s < 4; s++) {
                    int m = wm + s * 16 + lrow;
                    a[s][0] = As[k8 + lcol][m];
                    a[s][1] = As[k8 + lcol][m + 8];
                    a[s][2] = As[k8 + lcol + 4][m];
                    a[s][3] = As[k8 + lcol + 4][m + 8];
                }
#pragma unroll
                for (int t = 0; t < 4; t++) {
                    int nn = wn + t * 8 + lrow;
                    b[t][0] = Bs[k8 + lcol][nn];
                    b[t][1] = Bs[k8 + lcol + 4][nn];
                }
#pragma unroll
                for (int s = 0; s < 4; s++)
#pragma unroll
                    for (int t = 0; t < 4; t++)
                        mma_tf32(c[s][t], a[s], b[t]);
            }
            __syncthreads();
        }
    }

    // --- epilogue: relu(x + (acc + masked-bias-sum) * 0.2) ---
#pragma unroll
    for (int s = 0; s < 4; s++) {
#pragma unroll
        for (int h = 0; h < 2; h++) {
            int mloc = wm + s * 16 + lrow + h * 8;
            int grow = row0 + mloc;
            if (grow >= n) continue;
            float mk[NET];
#pragma unroll
            for (int et = 0; et < NET; et++) mk[et] = msk[et][mloc];
#pragma unroll
            for (int t = 0; t < 4; t++) {
                int ncol = wn + t * 8 + lcol * 2;
                float bs0 = 0.f, bs1 = 0.f;
#pragma unroll
                for (int et = 0; et < NET; et++) {
                    if (mk[et] > 0.f) {
                        bs0 += bsm[et][ncol];
                        bs1 += bsm[et][ncol + 1];
                    }
                }
                float c0 = c[s][t][h * 2 + 0];
                float c1 = c[s][t][h * 2 + 1];
                const float* xp = x + (size_t)grow * D + ncol;
                float xv0 = xp[0], xv1 = xp[1];
                float2 o;
                o.x = fmaxf(xv0 + (c0 + bs0) * 0.2f, 0.f);
                o.y = fmaxf(xv1 + (c1 + bs1) * 0.2f, 0.f);
                *reinterpret_cast<float2*>(out + (size_t)grow * D + ncol) = o;
            }
        }
    }
}

// ---------------------------------------------------------------------------
extern "C" void kernel_launch(void* const* d_in, const int* in_sizes, int n_in,
                              void* d_out, int out_size)
{
    const float* x = (const float*)d_in[0];
    int n = in_sizes[0] / D;
    if (n > MAXN) return;

    EdgeMeta em;
    WPtrs wp;
    const float *b[NET];
    int maxE = 0, totE = 0;
    for (int et = 0; et < NET; et++) {
        em.ef[et]  = (const float*)d_in[1 + 5 * et + 0];
        wp.W[et]   = (const float*)d_in[1 + 5 * et + 1];
        b[et]      = (const float*)d_in[1 + 5 * et + 2];
        em.src[et] = (const int*)  d_in[1 + 5 * et + 3];
        em.dst[et] = (const int*)  d_in[1 + 5 * et + 4];
        em.E[et]   = in_sizes[1 + 5 * et + 3];
        if (em.E[et] > maxE) maxE = em.E[et];
        totE += em.E[et];
    }
    if (totE > CAP_TOTAL) return;
    float* out = (float*)d_out;

    int nelem = NET * n;
    int nblk  = (nelem + 2047) / 2048;

    // conversions
    conv_x_kernel<<<(n * D / 4 + 255) / 256, 256>>>(x, n * D / 4);
    {
        dim3 grid((KW * D + 255) / 256, NET);
        conv_w_kernel<<<grid, 256>>>(wp, KW * D);
    }

    // CSR build
    zero_deg_kernel<<<(nelem + 255) / 256, 256>>>(nelem);
    {
        dim3 grid((maxE + 255) / 256, NET);
        count_kernel<<<grid, 256>>>(em, n);
    }
    scan_part_kernel<<<nblk, 256>>>(nelem);
    scan_top_kernel<<<1, 256>>>(nblk);
    scan_final_kernel<<<nblk, 256>>>(nelem);
    {
        dim3 grid((maxE + 255) / 256, NET);
        fill_kernel<<<grid, 256>>>(em, n);
    }

    // gather
    {
        int blocks = (nelem * 32 + 255) / 256;
        gather_kernel<<<blocks, 256>>>(em, n);
    }

    // fused GEMM + epilogue
    {
        int blocks = (n + BM - 1) / BM;
        gemm_epi_kernel<<<blocks, 256>>>(x, b[0], b[1], b[2], b[3], b[4], out, n);
    }
}

// round 4
// speedup vs baseline: 1.8949x; 1.1631x over previous
#include <cuda_runtime.h>
#include <cuda_fp16.h>
#include <cstdint>

#define D    128
#define DE   32
#define NET  5
#define MAXN 50000
#define CAP_TOTAL 4000000
#define KW   (D + DE)       // 160

// ---- scratch (device globals: allocation-free) ----
__device__ __half g_xh [(size_t)MAXN * D];            // fp16 op_feats
__device__ __half g_S1h[(size_t)NET * MAXN * D];      // fp16 per-etype mean of src feats
__device__ __half g_S2h[(size_t)NET * MAXN * DE];     // fp16 per-etype mean of edge feats
__device__ __half g_Wh [(size_t)NET * D * KW];        // fp16 weights, TRANSPOSED [et][n][k]
__device__ float  g_mask[(size_t)NET * MAXN];
__device__ int    g_deg[(size_t)NET * MAXN];
__device__ int    g_off[(size_t)NET * MAXN];
__device__ int    g_cur[(size_t)NET * MAXN];
__device__ int2   g_csr[(size_t)CAP_TOTAL];           // (src, edge_id)
__device__ int    g_total;

struct EdgeMeta {
    const int*   src[NET];
    const int*   dst[NET];
    const float* ef[NET];
    int          E[NET];
};
struct WPtrs { const float* W[NET]; };

// ---------------------------------------------------------------------------
// prep: x->fp16, W->fp16 transposed [n][k], zero degs & cursor
// ---------------------------------------------------------------------------
__global__ void prep_kernel(const float* __restrict__ x, WPtrs wp, int n)
{
    int i = blockIdx.x * blockDim.x + threadIdx.x;

    int tx = n * D / 8;
    if (i < tx) {
        float4 v0 = __ldg(reinterpret_cast<const float4*>(x) + 2 * i);
        float4 v1 = __ldg(reinterpret_cast<const float4*>(x) + 2 * i + 1);
        __half2 h[4];
        h[0] = __floats2half2_rn(v0.x, v0.y);
        h[1] = __floats2half2_rn(v0.z, v0.w);
        h[2] = __floats2half2_rn(v1.x, v1.y);
        h[3] = __floats2half2_rn(v1.z, v1.w);
        reinterpret_cast<uint4*>(g_xh)[i] = *reinterpret_cast<uint4*>(h);
    }
    if (i < NET * D * KW) {
        int et = i / (D * KW);
        int r  = i % (D * KW);
        int nn = r / KW;
        int k  = r % KW;
        const float* W = (et == 0) ? wp.W[0] : (et == 1) ? wp.W[1]
                       : (et == 2) ? wp.W[2] : (et == 3) ? wp.W[3] : wp.W[4];
        g_Wh[i] = __float2half_rn(__ldg(&W[k * D + nn]));
    }
    if (i < NET * n) g_deg[i] = 0;
    if (i == 0) g_total = 0;
}

// ---------------------------------------------------------------------------
// count degrees
// ---------------------------------------------------------------------------
__global__ void count_kernel(EdgeMeta em, int n)
{
    int et = blockIdx.y;
    int i  = blockIdx.x * blockDim.x + threadIdx.x;
    const int* dst = (et == 0) ? em.dst[0] : (et == 1) ? em.dst[1] : (et == 2) ? em.dst[2]
                   : (et == 3) ? em.dst[3] : em.dst[4];
    if (i < em.E[et]) atomicAdd(&g_deg[et * n + __ldg(&dst[i])], 1);
}

// ---------------------------------------------------------------------------
// alloc: segment offsets via block scan + one global atomic (order-free CSR)
// ---------------------------------------------------------------------------
__global__ void alloc_kernel(int nelem)
{
    __shared__ int wsum[8];
    int tid  = threadIdx.x;
    int i    = blockIdx.x * 256 + tid;
    int lane = tid & 31;
    int w    = tid >> 5;

    int d = (i < nelem) ? g_deg[i] : 0;
    int v = d;
#pragma unroll
    for (int o = 1; o < 32; o <<= 1) {
        int t = __shfl_up_sync(0xffffffffu, v, o);
        if (lane >= o) v += t;
    }
    if (lane == 31) wsum[w] = v;
    __syncthreads();
    if (tid == 0) {
        int s = 0;
#pragma unroll
        for (int j = 0; j < 8; j++) { int t = wsum[j]; wsum[j] = s; s += t; }
        int base = atomicAdd(&g_total, s);
#pragma unroll
        for (int j = 0; j < 8; j++) wsum[j] += base;
    }
    __syncthreads();
    int off = wsum[w] + v - d;   // exclusive within warp + block/global base
    if (i < nelem) { g_off[i] = off; g_cur[i] = off; }
}

// ---------------------------------------------------------------------------
// fill CSR
// ---------------------------------------------------------------------------
__global__ void fill_kernel(EdgeMeta em, int n)
{
    int et = blockIdx.y;
    int i  = blockIdx.x * blockDim.x + threadIdx.x;
    const int* dst = (et == 0) ? em.dst[0] : (et == 1) ? em.dst[1] : (et == 2) ? em.dst[2]
                   : (et == 3) ? em.dst[3] : em.dst[4];
    const int* src = (et == 0) ? em.src[0] : (et == 1) ? em.src[1] : (et == 2) ? em.src[2]
                   : (et == 3) ? em.src[3] : em.src[4];
    if (i < em.E[et]) {
        int d = __ldg(&dst[i]);
        int s = __ldg(&src[i]);
        int pos = atomicAdd(&g_cur[et * n + d], 1);
        g_csr[pos] = make_int2(s, i);
    }
}

// ---------------------------------------------------------------------------
// gather: one warp per (etype,node); HALF-WARP per edge (2 edges/iter),
// 16B x-row loads, fp32 accum, fp16 output means.
// ---------------------------------------------------------------------------
__global__ void __launch_bounds__(256)
gather_kernel(EdgeMeta em, int n)
{
    int gw   = (blockIdx.x * blockDim.x + threadIdx.x) >> 5;
    int lane = threadIdx.x & 31;
    if (gw >= NET * n) return;

    int et = gw / n;
    const float* __restrict__ ef =
        (et == 0) ? em.ef[0] : (et == 1) ? em.ef[1] : (et == 2) ? em.ef[2]
                  : (et == 3) ? em.ef[3] : em.ef[4];

    int beg = g_off[gw];
    int cnt = g_deg[gw];
    int end = beg + cnt;

    int half = lane >> 4;   // which edge of the pair
    int hl   = lane & 15;   // lane within half-warp

    float a1[8];
#pragma unroll
    for (int q = 0; q < 8; q++) a1[q] = 0.f;
    float2 a2 = make_float2(0.f, 0.f);

    for (int base = beg; base < end; base += 32) {
        int take = min(32, end - base);
        int2 mm = make_int2(0, 0);
        if (lane < take) mm = __ldg(&g_csr[base + lane]);
#pragma unroll 4
        for (int j = 0; j < take; j += 2) {
            int e    = j + half;
            int sidx = __shfl_sync(0xffffffffu, mm.x, e);
            int eidx = __shfl_sync(0xffffffffu, mm.y, e);
            if (e < take) {
                uint4 hv = __ldg(reinterpret_cast<const uint4*>(
                               g_xh + (size_t)sidx * D) + hl);
                __half2* hp = reinterpret_cast<__half2*>(&hv);
#pragma unroll
                for (int q = 0; q < 4; q++) {
                    float2 f = __half22float2(hp[q]);
                    a1[2 * q]     += f.x;
                    a1[2 * q + 1] += f.y;
                }
                float2 ev = __ldg(reinterpret_cast<const float2*>(
                                ef + (size_t)eidx * DE) + hl);
                a2.x += ev.x; a2.y += ev.y;
            }
        }
    }

    // combine the two half-warps (same feature chunk, different edges)
#pragma unroll
    for (int q = 0; q < 8; q++) a1[q] += __shfl_xor_sync(0xffffffffu, a1[q], 16);
    a2.x += __shfl_xor_sync(0xffffffffu, a2.x, 16);
    a2.y += __shfl_xor_sync(0xffffffffu, a2.y, 16);

    if (half == 0) {
        float inv = (cnt > 0) ? (1.0f / (float)cnt) : 0.0f;
        __half2 oh[4];
#pragma unroll
        for (int q = 0; q < 4; q++)
            oh[q] = __floats2half2_rn(a1[2 * q] * inv, a1[2 * q + 1] * inv);
        *(reinterpret_cast<uint4*>(g_S1h + (size_t)gw * D) + hl) =
            *reinterpret_cast<uint4*>(oh);
        __half2 e2 = __floats2half2_rn(a2.x * inv, a2.y * inv);
        *(reinterpret_cast<__half2*>(g_S2h + (size_t)gw * DE) + hl) = e2;
        if (lane == 0) g_mask[gw] = (cnt > 0) ? 1.0f : 0.0f;
    }
}

// ---------------------------------------------------------------------------
// fused GEMM (fp16 HMMA, fp32 accum) + epilogue.
// CTA 128x128; per-etype FULL-K (160) tiles in dynamic smem; 8 warps 2Mx4N,
// warp tile 64x32; mma m16n8k16.
// ---------------------------------------------------------------------------
#define BM  128
#define SAH 168   // half-stride per row (160 + 8 pad); 336B, 16B-aligned

__device__ __forceinline__ void mma_f16(float* c, const unsigned* a, const unsigned* b)
{
    asm volatile(
        "mma.sync.aligned.m16n8k16.row.col.f32.f16.f16.f32 "
        "{%0,%1,%2,%3}, {%4,%5,%6,%7}, {%8,%9}, {%0,%1,%2,%3};"
        : "+f"(c[0]), "+f"(c[1]), "+f"(c[2]), "+f"(c[3])
        : "r"(a[0]), "r"(a[1]), "r"(a[2]), "r"(a[3]),
          "r"(b[0]), "r"(b[1]));
}

__global__ void __launch_bounds__(256, 2)
gemm_epi_kernel(const float* __restrict__ x,
                const float* __restrict__ b0, const float* __restrict__ b1,
                const float* __restrict__ b2, const float* __restrict__ b3,
                const float* __restrict__ b4,
                float* __restrict__ out, int n)
{
    extern __shared__ __half sm[];
    __half* As = sm;                    // [BM][SAH]
    __half* Bs = sm + (size_t)BM * SAH; // [D][SAH]  (rows = n, cols = k)

    __shared__ float msk[NET][BM];
    __shared__ float bsm[NET][D];

    const float* bp[NET] = {b0, b1, b2, b3, b4};

    int tid  = threadIdx.x;
    int lane = tid & 31;
    int warp = tid >> 5;
    int wm   = (warp & 1) * 64;
    int wn   = (warp >> 1) * 32;
    int lrow = lane >> 2;
    int lcol = lane & 3;
    int row0 = blockIdx.x * BM;

#pragma unroll
    for (int et = 0; et < NET; et++) {
        if (tid < BM) {
            int row = row0 + tid;
            msk[et][tid] = (row < n) ? g_mask[(size_t)et * n + row] : 0.f;
        }
        if (tid < D) bsm[et][tid] = bp[et][tid];
    }

    float c[4][4][4];
#pragma unroll
    for (int s = 0; s < 4; s++)
#pragma unroll
        for (int t = 0; t < 4; t++)
#pragma unroll
            for (int r = 0; r < 4; r++) c[s][t][r] = 0.f;

    __syncthreads();

#pragma unroll 1
    for (int et = 0; et < NET; et++) {
        const __half* __restrict__ S1e = g_S1h + (size_t)et * n * D;
        const __half* __restrict__ S2e = g_S2h + (size_t)et * n * DE;
        const __half* __restrict__ Whe = g_Wh  + (size_t)et * D * KW;

        // load A tile: 128 rows x 160 halves (20 uint4 per row)
#pragma unroll
        for (int t = 0; t < 10; t++) {
            int idx = tid + t * 256;
            int row = idx / 20;
            int cc  = idx % 20;
            int grow = row0 + row;
            uint4 v = make_uint4(0u, 0u, 0u, 0u);
            if (grow < n) {
                v = (cc < 16)
                  ? __ldg(reinterpret_cast<const uint4*>(S1e + (size_t)grow * D)  + cc)
                  : __ldg(reinterpret_cast<const uint4*>(S2e + (size_t)grow * DE) + (cc - 16));
            }
            *reinterpret_cast<uint4*>(As + (size_t)row * SAH + cc * 8) = v;
        }
        // load B tile: 128 n-rows x 160 k halves (pre-transposed)
#pragma unroll
        for (int t = 0; t < 10; t++) {
            int idx = tid + t * 256;
            int row = idx / 20;
            int cc  = idx % 20;
            uint4 v = __ldg(reinterpret_cast<const uint4*>(Whe + (size_t)row * KW) + cc);
            *reinterpret_cast<uint4*>(Bs + (size_t)row * SAH + cc * 8) = v;
        }
        __syncthreads();

#pragma unroll
        for (int kk = 0; kk < 10; kk++) {
            int k0 = kk * 16;
            unsigned a[4][4], b[4][2];
#pragma unroll
            for (int s = 0; s < 4; s++) {
                int m = wm + s * 16 + lrow;
                const __half* p0 = As + (size_t)m * SAH + k0 + 2 * lcol;
                a[s][0] = *reinterpret_cast<const unsigned*>(p0);
                a[s][1] = *reinterpret_cast<const unsigned*>(p0 + 8 * SAH);
                a[s][2] = *reinterpret_cast<const unsigned*>(p0 + 8);
                a[s][3] = *reinterpret_cast<const unsigned*>(p0 + 8 * SAH + 8);
            }
#pragma unroll
            for (int t = 0; t < 4; t++) {
                int nn = wn + t * 8 + lrow;
                const __half* p0 = Bs + (size_t)nn * SAH + k0 + 2 * lcol;
                b[t][0] = *reinterpret_cast<const unsigned*>(p0);
                b[t][1] = *reinterpret_cast<const unsigned*>(p0 + 8);
            }
#pragma unroll
            for (int s = 0; s < 4; s++)
#pragma unroll
                for (int t = 0; t < 4; t++)
                    mma_f16(c[s][t], a[s], b[t]);
        }
        __syncthreads();
    }

    // epilogue: relu(x + (acc + masked-bias-sum) * 0.2)
#pragma unroll
    for (int s = 0; s < 4; s++) {
#pragma unroll
        for (int h = 0; h < 2; h++) {
            int mloc = wm + s * 16 + lrow + h * 8;
            int grow = row0 + mloc;
            if (grow >= n) continue;
            float mk[NET];
#pragma unroll
            for (int et = 0; et < NET; et++) mk[et] = msk[et][mloc];
#pragma unroll
            for (int t = 0; t < 4; t++) {
                int ncol = wn + t * 8 + lcol * 2;
                float bs0 = 0.f, bs1 = 0.f;
#pragma unroll
                for (int et = 0; et < NET; et++) {
                    if (mk[et] > 0.f) {
                        bs0 += bsm[et][ncol];
                        bs1 += bsm[et][ncol + 1];
                    }
                }
                float c0 = c[s][t][h * 2 + 0];
                float c1 = c[s][t][h * 2 + 1];
                const float* xp = x + (size_t)grow * D + ncol;
                float2 o;
                o.x = fmaxf(xp[0] + (c0 + bs0) * 0.2f, 0.f);
                o.y = fmaxf(xp[1] + (c1 + bs1) * 0.2f, 0.f);
                *reinterpret_cast<float2*>(out + (size_t)grow * D + ncol) = o;
            }
        }
    }
}

// ---------------------------------------------------------------------------
extern "C" void kernel_launch(void* const* d_in, const int* in_sizes, int n_in,
                              void* d_out, int out_size)
{
    const float* x = (const float*)d_in[0];
    int n = in_sizes[0] / D;
    if (n > MAXN) return;

    EdgeMeta em;
    WPtrs wp;
    const float* b[NET];
    int maxE = 0, totE = 0;
    for (int et = 0; et < NET; et++) {
        em.ef[et]  = (const float*)d_in[1 + 5 * et + 0];
        wp.W[et]   = (const float*)d_in[1 + 5 * et + 1];
        b[et]      = (const float*)d_in[1 + 5 * et + 2];
        em.src[et] = (const int*)  d_in[1 + 5 * et + 3];
        em.dst[et] = (const int*)  d_in[1 + 5 * et + 4];
        em.E[et]   = in_sizes[1 + 5 * et + 3];
        if (em.E[et] > maxE) maxE = em.E[et];
        totE += em.E[et];
    }
    if (totE > CAP_TOTAL) return;
    float* out = (float*)d_out;

    int nelem = NET * n;

    // enable 86KB dynamic smem for the GEMM (idempotent)
    static int smem_bytes = 2 * BM * SAH * (int)sizeof(__half);
    cudaFuncSetAttribute(gemm_epi_kernel,
                         cudaFuncAttributeMaxDynamicSharedMemorySize, smem_bytes);

    // 1) prep (x->fp16, W->fp16 transposed, zero)
    {
        int work = n * D / 8;
        if (NET * D * KW > work) work = NET * D * KW;
        if (nelem > work) work = nelem;
        prep_kernel<<<(work + 255) / 256, 256>>>(x, wp, n);
    }
    // 2) count
    {
        dim3 grid((maxE + 255) / 256, NET);
        count_kernel<<<grid, 256>>>(em, n);
    }
    // 3) alloc (block scan + global atomic)
    alloc_kernel<<<(nelem + 255) / 256, 256>>>(nelem);
    // 4) fill
    {
        dim3 grid((maxE + 255) / 256, NET);
        fill_kernel<<<grid, 256>>>(em, n);
    }
    // 5) gather
    {
        int blocks = (nelem * 32 + 255) / 256;
        gather_kernel<<<blocks, 256>>>(em, n);
    }
    // 6) fused GEMM + epilogue
    {
        int blocks = (n + BM - 1) / BM;
        gemm_epi_kernel<<<blocks, 256, smem_bytes>>>(
            x, b[0], b[1], b[2], b[3], b[4], out, n);
    }
}